// round 12
// baseline (speedup 1.0000x reference)
#include <cuda_runtime.h>
#include <cuda_bf16.h>
#include <math.h>
#include <stdint.h>

#define F 128
#define MAXN 100000

// Scratch: Wh tables as bf16x2 (row = 64 uint32 = 256 B)
__device__ uint32_t g_whb_ref[(size_t)MAXN * 64];
__device__ uint32_t g_whb_dir[(size_t)MAXN * 64];
__device__ float g_s_ref[MAXN];
__device__ float g_t_ref[MAXN];
__device__ float g_s_dir[MAXN];
__device__ float g_t_dir[MAXN];

__device__ __forceinline__ float leakyf(float x) { return x >= 0.f ? x : 0.2f * x; }
__device__ __forceinline__ float sigmoidf_(float x) { return 1.0f / (1.0f + __expf(-x)); }

__device__ __forceinline__ void mma_tf32(float& c0, float& c1, float& c2, float& c3,
                                         uint32_t a0, uint32_t a1, uint32_t a2, uint32_t a3,
                                         uint32_t b0, uint32_t b1) {
    asm volatile(
        "mma.sync.aligned.m16n8k8.row.col.f32.tf32.tf32.f32 "
        "{%0,%1,%2,%3},{%4,%5,%6,%7},{%8,%9},{%0,%1,%2,%3};"
        : "+f"(c0), "+f"(c1), "+f"(c2), "+f"(c3)
        : "r"(a0), "r"(a1), "r"(a2), "r"(a3), "r"(b0), "r"(b1));
}

__device__ __forceinline__ void ffma2(unsigned long long& acc,
                                      unsigned long long v,
                                      unsigned long long w) {
    asm("fma.rn.f32x2 %0, %1, %2, %0;" : "+l"(acc) : "l"(v), "l"(w));
}
__device__ __forceinline__ unsigned long long packf2(float lo, float hi) {
    unsigned long long r;
    asm("mov.b64 %0, {%1, %2};" : "=l"(r) : "f"(lo), "f"(hi));
    return r;
}
// bf16x2 -> packed f32x2: exact, no CVT
__device__ __forceinline__ unsigned long long bf2f2(uint32_t p) {
    uint32_t lo = p << 16;
    uint32_t hi = p & 0xFFFF0000u;
    unsigned long long r;
    asm("mov.b64 %0, {%1, %2};" : "=l"(r) : "r"(lo), "r"(hi));
    return r;
}
__device__ __forceinline__ unsigned long long addf2(unsigned long long a,
                                                    unsigned long long b) {
    unsigned long long r;
    asm("add.rn.f32x2 %0, %1, %2;" : "=l"(r) : "l"(a), "l"(b));
    return r;
}
__device__ __forceinline__ unsigned long long shflx64(unsigned long long v, int m) {
    uint32_t lo = (uint32_t)v, hi = (uint32_t)(v >> 32);
    lo = __shfl_xor_sync(0xffffffffu, lo, m);
    hi = __shfl_xor_sync(0xffffffffu, hi, m);
    return ((unsigned long long)hi << 32) | lo;
}

__device__ __forceinline__ void cp16(uint32_t smem_addr, const void* gptr) {
    asm volatile("cp.async.ca.shared.global [%0], [%1], 16;"
                 :: "r"(smem_addr), "l"(gptr));
}
__device__ __forceinline__ void cp_commit() {
    asm volatile("cp.async.commit_group;" ::: "memory");
}
template <int NN>
__device__ __forceinline__ void cp_wait() {
    asm volatile("cp.async.wait_group %0;" :: "n"(NN) : "memory");
}

// ---------------------------------------------------------------------------
// Kernel 1: FUSED dual GEMM via tf32 MMA with cp.async pipeline.
// (R11 version verbatim — measured ~60us)
// ---------------------------------------------------------------------------
#define BK 16
#define ASTRIDE 20
#define BSTRIDE 136

__global__ __launch_bounds__(256, 2)
void gemm_tf32_kernel(const float* __restrict__ h,
                      const float* __restrict__ Wref,
                      const float* __restrict__ Wdir,
                      const float* __restrict__ a_ref,
                      const float* __restrict__ a_dir,
                      int N)
{
    const int m0 = blockIdx.x * 64;

    __shared__ uint32_t As[2][64][ASTRIDE];
    __shared__ uint32_t Bs[2][2][BK][BSTRIDE];
    __shared__ float s_sm[2][64];
    __shared__ float t_sm[2][64];

    const int tid = threadIdx.x;
    const int warp = tid >> 5;
    const int lane = tid & 31;
    const int gid = lane >> 2;
    const int tig = lane & 3;
    const int wm = warp & 1;
    const int wn = warp >> 1;

    if (tid < 128) {
        s_sm[tid >> 6][tid & 63] = 0.f;
        t_sm[tid >> 6][tid & 63] = 0.f;
    }

    float acc[2][2][4][4];
#pragma unroll
    for (int mm = 0; mm < 2; mm++)
#pragma unroll
        for (int i = 0; i < 2; i++)
#pragma unroll
            for (int j = 0; j < 4; j++)
#pragma unroll
                for (int r = 0; r < 4; r++) acc[mm][i][j][r] = 0.f;

    const int am = tid >> 2;
    const int ac = tid & 3;
    int arow_g = m0 + am;
    if (arow_g >= N) arow_g = N - 1;
    const uint32_t asm_base = (uint32_t)__cvta_generic_to_shared(&As[0][0][0]);
    const uint32_t a_dst_off = (uint32_t)((am * ASTRIDE + ac * 4) * 4);
    const uint32_t a_stage_bytes = 64 * ASTRIDE * 4;

    const uint32_t bsm_base = (uint32_t)__cvta_generic_to_shared(&Bs[0][0][0][0]);
    const uint32_t b_stage_bytes = 2 * BK * BSTRIDE * 4;
    int bmm[4], bk_[4], bc[4];
#pragma unroll
    for (int rep = 0; rep < 4; rep++) {
        int idx = tid + rep * 256;
        bmm[rep] = idx >> 9;
        int r = idx & 511;
        bk_[rep] = r >> 5;
        bc[rep] = r & 31;
    }

    auto copy_tile = [&](int kt, int st) {
        cp16(asm_base + st * a_stage_bytes + a_dst_off,
             &h[(size_t)arow_g * F + kt * BK + ac * 4]);
#pragma unroll
        for (int rep = 0; rep < 4; rep++) {
            const float* W = bmm[rep] ? Wdir : Wref;
            uint32_t dst = bsm_base + st * b_stage_bytes +
                (uint32_t)(((bmm[rep] * BK + bk_[rep]) * BSTRIDE + bc[rep] * 4) * 4);
            cp16(dst, &W[(size_t)(kt * BK + bk_[rep]) * F + bc[rep] * 4]);
        }
    };

    copy_tile(0, 0);
    cp_commit();
    copy_tile(1, 1);
    cp_commit();

#pragma unroll
    for (int kt = 0; kt < F / BK; ++kt) {
        if (kt == F / BK - 1) cp_wait<0>(); else cp_wait<1>();
        __syncthreads();

        const int st = kt & 1;
#pragma unroll
        for (int ks = 0; ks < 2; ks++) {
            const int kk = ks * 8;
            uint32_t afr[2][4];
#pragma unroll
            for (int mt = 0; mt < 2; mt++) {
                int mb = wm * 32 + mt * 16;
                afr[mt][0] = As[st][mb + gid][kk + tig];
                afr[mt][1] = As[st][mb + gid + 8][kk + tig];
                afr[mt][2] = As[st][mb + gid][kk + tig + 4];
                afr[mt][3] = As[st][mb + gid + 8][kk + tig + 4];
            }
#pragma unroll
            for (int nt = 0; nt < 4; nt++) {
                int nb = wn * 32 + nt * 8;
#pragma unroll
                for (int mm = 0; mm < 2; mm++) {
                    uint32_t b0 = Bs[st][mm][kk + tig][nb + gid];
                    uint32_t b1 = Bs[st][mm][kk + tig + 4][nb + gid];
#pragma unroll
                    for (int mt = 0; mt < 2; mt++) {
                        mma_tf32(acc[mm][mt][nt][0], acc[mm][mt][nt][1],
                                 acc[mm][mt][nt][2], acc[mm][mt][nt][3],
                                 afr[mt][0], afr[mt][1], afr[mt][2], afr[mt][3], b0, b1);
                    }
                }
            }
        }
        __syncthreads();
        if (kt + 2 < F / BK) {
            copy_tile(kt + 2, st);
            cp_commit();
        }
    }

#pragma unroll
    for (int mm = 0; mm < 2; mm++) {
        const float* av = (mm == 0) ? a_ref : a_dir;
        uint32_t* outb = (mm == 0) ? g_whb_ref : g_whb_dir;
        float sp[2][2] = {{0.f, 0.f}, {0.f, 0.f}};
        float tp[2][2] = {{0.f, 0.f}, {0.f, 0.f}};

#pragma unroll
        for (int mt = 0; mt < 2; mt++) {
            int r0 = m0 + wm * 32 + mt * 16 + gid;
            int r1 = r0 + 8;
#pragma unroll
            for (int nt = 0; nt < 4; nt++) {
                int col = wn * 32 + nt * 8 + tig * 2;
                float as0 = av[col], as1 = av[col + 1];
                float an0 = av[128 + col], an1 = av[128 + col + 1];
                float c0 = acc[mm][mt][nt][0], c1 = acc[mm][mt][nt][1];
                float c2 = acc[mm][mt][nt][2], c3 = acc[mm][mt][nt][3];
                sp[mt][0] += c0 * as0 + c1 * as1;
                tp[mt][0] += c0 * an0 + c1 * an1;
                sp[mt][1] += c2 * as0 + c3 * as1;
                tp[mt][1] += c2 * an0 + c3 * an1;
                if (r0 < N) {
                    __nv_bfloat162 p = __float22bfloat162_rn(make_float2(c0, c1));
                    outb[(size_t)r0 * 64 + (col >> 1)] = *reinterpret_cast<uint32_t*>(&p);
                }
                if (r1 < N) {
                    __nv_bfloat162 p = __float22bfloat162_rn(make_float2(c2, c3));
                    outb[(size_t)r1 * 64 + (col >> 1)] = *reinterpret_cast<uint32_t*>(&p);
                }
            }
        }

#pragma unroll
        for (int mt = 0; mt < 2; mt++)
#pragma unroll
            for (int rr = 0; rr < 2; rr++) {
#pragma unroll
                for (int off = 1; off <= 2; off <<= 1) {
                    sp[mt][rr] += __shfl_xor_sync(0xffffffffu, sp[mt][rr], off);
                    tp[mt][rr] += __shfl_xor_sync(0xffffffffu, tp[mt][rr], off);
                }
                if (tig == 0) {
                    int lr = wm * 32 + mt * 16 + gid + rr * 8;
                    atomicAdd(&s_sm[mm][lr], sp[mt][rr]);
                    atomicAdd(&t_sm[mm][lr], tp[mt][rr]);
                }
            }
    }
    __syncthreads();

    if (tid < 128) {
        int mm = tid >> 6;
        int r = tid & 63;
        int gr = m0 + r;
        if (gr < N) {
            if (mm == 0) { g_s_ref[gr] = s_sm[0][r]; g_t_ref[gr] = t_sm[0][r]; }
            else         { g_s_dir[gr] = s_sm[1][r]; g_t_dir[gr] = t_sm[1][r]; }
        }
    }
}

// ---------------------------------------------------------------------------
// Kernel 2: fused attention + gather + sigmoid + average. One warp per node.
// Half-warp pairing: lanes 0-15 process neighbor k, lanes 16-31 neighbor k+1;
// each lane loads 16B (8 bf16 cols) per neighbor. Entries pre-packed as
// {w, w, idx, 0} so one LDS.128 feeds weight-pair + index.
// ---------------------------------------------------------------------------
__global__ __launch_bounds__(128, 10)
void gather_kernel(const int* __restrict__ ref_nb,   // [N,4,10]
                   const int* __restrict__ ref_cnt,  // [N,4]
                   const int* __restrict__ dir_nb,   // [N,32]
                   const int* __restrict__ dir_cnt,  // [N]
                   float* __restrict__ out,
                   int N)
{
    __shared__ float4 s_ref[4][42];
    __shared__ float4 s_dir[4][32];
    const unsigned FULL = 0xffffffffu;
    const int wid = threadIdx.x >> 5;
    const int lane = threadIdx.x & 31;
    const int n = (blockIdx.x * blockDim.x + threadIdx.x) >> 5;
    if (n >= N) return;

    // ---- prologue loads ----------------------------------------------------
    int4 rc = *reinterpret_cast<const int4*>(&ref_cnt[n * 4]);
    int idx1 = ref_nb[(size_t)n * 40 + lane];
    int idx2 = (lane < 8) ? ref_nb[(size_t)n * 40 + 32 + lane] : 0;
    int dcnt = dir_cnt[n];
    int didx = dir_nb[(size_t)n * 32 + lane];
    float sref = g_s_ref[n];
    float sdir = g_s_dir[n];

    const int d1 = lane / 10;
    const int k1 = lane - d1 * 10;
    int cd1 = (d1 == 0) ? rc.x : (d1 == 1) ? rc.y : (d1 == 2) ? rc.z : rc.w;
    bool v1 = (k1 < cd1);
    bool v2 = (lane < 8) && ((lane + 2) < rc.w);
    bool dval = (lane < dcnt);

    float tv1 = v1 ? g_t_ref[idx1] : 0.f;
    float tv2 = v2 ? g_t_ref[idx2] : 0.f;
    float td  = dval ? g_t_dir[didx] : 0.f;

    // ---- per-depth t sums via windowed shfl --------------------------------
    float x1 = tv1 + __shfl_down_sync(FULL, tv1, 1);
    float x2 = x1 + __shfl_down_sync(FULL, x1, 2);
    float x4 = x2 + __shfl_down_sync(FULL, x2, 4);
    float b = tv2;
    b += __shfl_xor_sync(FULL, b, 1);
    b += __shfl_xor_sync(FULL, b, 2);
    b += __shfl_xor_sync(FULL, b, 4);
    float S0 = __shfl_sync(FULL, x4, 0)  + __shfl_sync(FULL, x1, 8);
    float S1 = __shfl_sync(FULL, x4, 10) + __shfl_sync(FULL, x1, 18);
    float S2 = __shfl_sync(FULL, x4, 20) + __shfl_sync(FULL, x1, 28);
    float S3 = __shfl_sync(FULL, x1, 30) + __shfl_sync(FULL, b, 0);

    // ---- ref softmax over 4 depths ------------------------------------------
    float c0f = (float)max(rc.x, 1), c1f = (float)max(rc.y, 1);
    float c2f = (float)max(rc.z, 1), c3f = (float)max(rc.w, 1);
    float e0 = leakyf(sref + S0 / c0f);
    float e1 = leakyf(sref + S1 / c1f);
    float e2 = leakyf(sref + S2 / c2f);
    float e3 = leakyf(sref + S3 / c3f);
    float m4 = fmaxf(fmaxf(e0, e1), fmaxf(e2, e3));
    float x0e = __expf(e0 - m4), x1e = __expf(e1 - m4);
    float x2e = __expf(e2 - m4), x3e = __expf(e3 - m4);
    float den = x0e + x1e + x2e + x3e;
    float wd0 = x0e / (den * c0f), wd1 = x1e / (den * c1f);
    float wd2 = x2e / (den * c2f), wd3 = x3e / (den * c3f);

    float w1 = (d1 == 0) ? wd0 : (d1 == 1) ? wd1 : (d1 == 2) ? wd2 : wd3;
    float w2 = wd3;

    // ---- dir softmax ---------------------------------------------------------
    float exd = dval ? __expf(leakyf(sdir + td)) : 0.f;
    float dend = exd;
#pragma unroll
    for (int off = 16; off; off >>= 1) dend += __shfl_xor_sync(FULL, dend, off);
    float alpha = exd / dend;

    // ---- compaction: entries {w, w, idx, 0}; pad ref to even ----------------
    int P1 = rc.x, P2 = P1 + rc.y, P3 = P2 + rc.z;
    int nref = P3 + rc.w;
    int dst1 = ((d1 == 0) ? 0 : (d1 == 1) ? P1 : (d1 == 2) ? P2 : P3) + k1;
    if (v1) s_ref[wid][dst1] = make_float4(w1, w1, __int_as_float(idx1), 0.f);
    if (v2) s_ref[wid][P3 + lane + 2] = make_float4(w2, w2, __int_as_float(idx2), 0.f);
    if ((nref & 1) && lane == 0)
        s_ref[wid][nref] = make_float4(0.f, 0.f, __int_as_float(0), 0.f);
    // dir: invalid lanes carry alpha == 0; idx always in-range.
    s_dir[wid][lane] = make_float4(alpha, alpha, __int_as_float(didx), 0.f);
    __syncwarp();

    // ---- gathers: half-warp pairing, LDG.128 per lane ------------------------
    const int half = lane >> 4;
    const int lc = lane & 15;
    const char* baseR = (const char*)g_whb_ref + lc * 16;
    const char* baseD = (const char*)g_whb_dir + lc * 16;

    unsigned long long r0 = 0, r1 = 0, r2 = 0, r3 = 0;   // ref: cols lc*8+0..7
    unsigned long long d0 = 0, d1a = 0, d2 = 0, d3 = 0;  // dir

    const int npR = (nref + 1) & ~1;
    const int npD = (dcnt + 1) & ~1;

    int k = 0;
    for (; k + 4 <= npD; k += 4) {
        float4 eA = s_dir[wid][k + half];
        float4 eB = s_dir[wid][k + 2 + half];
        uint4 vA = *reinterpret_cast<const uint4*>(
            baseD + (size_t)__float_as_int(eA.z) * 256);
        uint4 vB = *reinterpret_cast<const uint4*>(
            baseD + (size_t)__float_as_int(eB.z) * 256);
        unsigned long long wA = packf2(eA.x, eA.y);
        unsigned long long wB = packf2(eB.x, eB.y);
        ffma2(d0, bf2f2(vA.x), wA); ffma2(d1a, bf2f2(vA.y), wA);
        ffma2(d2, bf2f2(vA.z), wA); ffma2(d3, bf2f2(vA.w), wA);
        ffma2(d0, bf2f2(vB.x), wB); ffma2(d1a, bf2f2(vB.y), wB);
        ffma2(d2, bf2f2(vB.z), wB); ffma2(d3, bf2f2(vB.w), wB);
    }
    if (k < npD) {
        float4 e = s_dir[wid][k + half];
        uint4 v = *reinterpret_cast<const uint4*>(
            baseD + (size_t)__float_as_int(e.z) * 256);
        unsigned long long w = packf2(e.x, e.y);
        ffma2(d0, bf2f2(v.x), w); ffma2(d1a, bf2f2(v.y), w);
        ffma2(d2, bf2f2(v.z), w); ffma2(d3, bf2f2(v.w), w);
    }

    k = 0;
    for (; k + 4 <= npR; k += 4) {
        float4 eA = s_ref[wid][k + half];
        float4 eB = s_ref[wid][k + 2 + half];
        uint4 vA = *reinterpret_cast<const uint4*>(
            baseR + (size_t)__float_as_int(eA.z) * 256);
        uint4 vB = *reinterpret_cast<const uint4*>(
            baseR + (size_t)__float_as_int(eB.z) * 256);
        unsigned long long wA = packf2(eA.x, eA.y);
        unsigned long long wB = packf2(eB.x, eB.y);
        ffma2(r0, bf2f2(vA.x), wA); ffma2(r1, bf2f2(vA.y), wA);
        ffma2(r2, bf2f2(vA.z), wA); ffma2(r3, bf2f2(vA.w), wA);
        ffma2(r0, bf2f2(vB.x), wB); ffma2(r1, bf2f2(vB.y), wB);
        ffma2(r2, bf2f2(vB.z), wB); ffma2(r3, bf2f2(vB.w), wB);
    }
    if (k < npR) {
        float4 e = s_ref[wid][k + half];
        uint4 v = *reinterpret_cast<const uint4*>(
            baseR + (size_t)__float_as_int(e.z) * 256);
        unsigned long long w = packf2(e.x, e.y);
        ffma2(r0, bf2f2(v.x), w); ffma2(r1, bf2f2(v.y), w);
        ffma2(r2, bf2f2(v.z), w); ffma2(r3, bf2f2(v.w), w);
    }

    // ---- combine halves (lanes l and l+16 hold partials for same cols) ------
    r0 = addf2(r0, shflx64(r0, 16));
    r1 = addf2(r1, shflx64(r1, 16));
    r2 = addf2(r2, shflx64(r2, 16));
    r3 = addf2(r3, shflx64(r3, 16));
    d0 = addf2(d0, shflx64(d0, 16));
    d1a = addf2(d1a, shflx64(d1a, 16));
    d2 = addf2(d2, shflx64(d2, 16));
    d3 = addf2(d3, shflx64(d3, 16));

    // ---- output: lane covers cols lc*8 + half*4 .. +3 ------------------------
    unsigned long long ua = half ? r2 : r0;
    unsigned long long ub = half ? r3 : r1;
    unsigned long long va = half ? d2 : d0;
    unsigned long long vb = half ? d3 : d1a;
    float2 fa = *reinterpret_cast<float2*>(&ua);
    float2 fb = *reinterpret_cast<float2*>(&ub);
    float2 ga = *reinterpret_cast<float2*>(&va);
    float2 gb = *reinterpret_cast<float2*>(&vb);

    float4 o;
    o.x = 0.5f * (sigmoidf_(fa.x) + sigmoidf_(ga.x));
    o.y = 0.5f * (sigmoidf_(fa.y) + sigmoidf_(ga.y));
    o.z = 0.5f * (sigmoidf_(fb.x) + sigmoidf_(gb.x));
    o.w = 0.5f * (sigmoidf_(fb.y) + sigmoidf_(gb.y));
    *reinterpret_cast<float4*>(&out[(size_t)n * F + lc * 8 + half * 4]) = o;
}

// ---------------------------------------------------------------------------
extern "C" void kernel_launch(void* const* d_in, const int* in_sizes, int n_in,
                              void* d_out, int out_size)
{
    const float* h     = (const float*)d_in[0];
    const float* W_ref = (const float*)d_in[1];
    const float* a_ref = (const float*)d_in[2];
    const float* W_dir = (const float*)d_in[3];
    const float* a_dir = (const float*)d_in[4];
    const int* ref_nb  = (const int*)d_in[5];
    const int* ref_cnt = (const int*)d_in[6];
    const int* dir_nb  = (const int*)d_in[7];
    const int* dir_cnt = (const int*)d_in[8];
    float* out = (float*)d_out;

    const int N = in_sizes[0] / F;

    gemm_tf32_kernel<<<(N + 63) / 64, 256>>>(h, W_ref, W_dir, a_ref, a_dir, N);

    const int nwb = (N * 32 + 127) / 128;  // one warp per node, 4 warps/block
    gather_kernel<<<nwb, 128>>>(ref_nb, ref_cnt, dir_nb, dir_cnt, out, N);
}

// round 13
// speedup vs baseline: 1.1374x; 1.1374x over previous
#include <cuda_runtime.h>
#include <cuda_bf16.h>
#include <math.h>
#include <stdint.h>

#define F 128
#define MAXN 100000

// Scratch: Wh tables as bf16x2 (row = 64 uint32 = 256 B)
__device__ uint32_t g_whb_ref[(size_t)MAXN * 64];
__device__ uint32_t g_whb_dir[(size_t)MAXN * 64];
__device__ float g_s_ref[MAXN];
__device__ float g_t_ref[MAXN];
__device__ float g_s_dir[MAXN];
__device__ float g_t_dir[MAXN];

__device__ __forceinline__ float leakyf(float x) { return x >= 0.f ? x : 0.2f * x; }
__device__ __forceinline__ float sigmoidf_(float x) { return 1.0f / (1.0f + __expf(-x)); }

__device__ __forceinline__ void mma_tf32(float& c0, float& c1, float& c2, float& c3,
                                         uint32_t a0, uint32_t a1, uint32_t a2, uint32_t a3,
                                         uint32_t b0, uint32_t b1) {
    asm volatile(
        "mma.sync.aligned.m16n8k8.row.col.f32.tf32.tf32.f32 "
        "{%0,%1,%2,%3},{%4,%5,%6,%7},{%8,%9},{%0,%1,%2,%3};"
        : "+f"(c0), "+f"(c1), "+f"(c2), "+f"(c3)
        : "r"(a0), "r"(a1), "r"(a2), "r"(a3), "r"(b0), "r"(b1));
}

__device__ __forceinline__ void ffma2(unsigned long long& acc,
                                      unsigned long long v,
                                      unsigned long long w) {
    asm("fma.rn.f32x2 %0, %1, %2, %0;" : "+l"(acc) : "l"(v), "l"(w));
}
__device__ __forceinline__ unsigned long long packf2(float lo, float hi) {
    unsigned long long r;
    asm("mov.b64 %0, {%1, %2};" : "=l"(r) : "f"(lo), "f"(hi));
    return r;
}
// bf16x2 -> packed f32x2: exact, no CVT
__device__ __forceinline__ unsigned long long bf2f2(uint32_t p) {
    uint32_t lo = p << 16;
    uint32_t hi = p & 0xFFFF0000u;
    unsigned long long r;
    asm("mov.b64 %0, {%1, %2};" : "=l"(r) : "r"(lo), "r"(hi));
    return r;
}

__device__ __forceinline__ void cp16(uint32_t smem_addr, const void* gptr) {
    asm volatile("cp.async.ca.shared.global [%0], [%1], 16;"
                 :: "r"(smem_addr), "l"(gptr));
}
__device__ __forceinline__ void cp_commit() {
    asm volatile("cp.async.commit_group;" ::: "memory");
}
template <int NN>
__device__ __forceinline__ void cp_wait() {
    asm volatile("cp.async.wait_group %0;" :: "n"(NN) : "memory");
}

// ---------------------------------------------------------------------------
// Kernel 1: FUSED dual GEMM via tf32 MMA with cp.async pipeline.
// (R11 version verbatim — measured ~60us)
// ---------------------------------------------------------------------------
#define BK 16
#define ASTRIDE 20
#define BSTRIDE 136

__global__ __launch_bounds__(256, 2)
void gemm_tf32_kernel(const float* __restrict__ h,
                      const float* __restrict__ Wref,
                      const float* __restrict__ Wdir,
                      const float* __restrict__ a_ref,
                      const float* __restrict__ a_dir,
                      int N)
{
    const int m0 = blockIdx.x * 64;

    __shared__ uint32_t As[2][64][ASTRIDE];
    __shared__ uint32_t Bs[2][2][BK][BSTRIDE];
    __shared__ float s_sm[2][64];
    __shared__ float t_sm[2][64];

    const int tid = threadIdx.x;
    const int warp = tid >> 5;
    const int lane = tid & 31;
    const int gid = lane >> 2;
    const int tig = lane & 3;
    const int wm = warp & 1;
    const int wn = warp >> 1;

    if (tid < 128) {
        s_sm[tid >> 6][tid & 63] = 0.f;
        t_sm[tid >> 6][tid & 63] = 0.f;
    }

    float acc[2][2][4][4];
#pragma unroll
    for (int mm = 0; mm < 2; mm++)
#pragma unroll
        for (int i = 0; i < 2; i++)
#pragma unroll
            for (int j = 0; j < 4; j++)
#pragma unroll
                for (int r = 0; r < 4; r++) acc[mm][i][j][r] = 0.f;

    const int am = tid >> 2;
    const int ac = tid & 3;
    int arow_g = m0 + am;
    if (arow_g >= N) arow_g = N - 1;
    const uint32_t asm_base = (uint32_t)__cvta_generic_to_shared(&As[0][0][0]);
    const uint32_t a_dst_off = (uint32_t)((am * ASTRIDE + ac * 4) * 4);
    const uint32_t a_stage_bytes = 64 * ASTRIDE * 4;

    const uint32_t bsm_base = (uint32_t)__cvta_generic_to_shared(&Bs[0][0][0][0]);
    const uint32_t b_stage_bytes = 2 * BK * BSTRIDE * 4;
    int bmm[4], bk_[4], bc[4];
#pragma unroll
    for (int rep = 0; rep < 4; rep++) {
        int idx = tid + rep * 256;
        bmm[rep] = idx >> 9;
        int r = idx & 511;
        bk_[rep] = r >> 5;
        bc[rep] = r & 31;
    }

    auto copy_tile = [&](int kt, int st) {
        cp16(asm_base + st * a_stage_bytes + a_dst_off,
             &h[(size_t)arow_g * F + kt * BK + ac * 4]);
#pragma unroll
        for (int rep = 0; rep < 4; rep++) {
            const float* W = bmm[rep] ? Wdir : Wref;
            uint32_t dst = bsm_base + st * b_stage_bytes +
                (uint32_t)(((bmm[rep] * BK + bk_[rep]) * BSTRIDE + bc[rep] * 4) * 4);
            cp16(dst, &W[(size_t)(kt * BK + bk_[rep]) * F + bc[rep] * 4]);
        }
    };

    copy_tile(0, 0);
    cp_commit();
    copy_tile(1, 1);
    cp_commit();

#pragma unroll
    for (int kt = 0; kt < F / BK; ++kt) {
        if (kt == F / BK - 1) cp_wait<0>(); else cp_wait<1>();
        __syncthreads();

        const int st = kt & 1;
#pragma unroll
        for (int ks = 0; ks < 2; ks++) {
            const int kk = ks * 8;
            uint32_t afr[2][4];
#pragma unroll
            for (int mt = 0; mt < 2; mt++) {
                int mb = wm * 32 + mt * 16;
                afr[mt][0] = As[st][mb + gid][kk + tig];
                afr[mt][1] = As[st][mb + gid + 8][kk + tig];
                afr[mt][2] = As[st][mb + gid][kk + tig + 4];
                afr[mt][3] = As[st][mb + gid + 8][kk + tig + 4];
            }
#pragma unroll
            for (int nt = 0; nt < 4; nt++) {
                int nb = wn * 32 + nt * 8;
#pragma unroll
                for (int mm = 0; mm < 2; mm++) {
                    uint32_t b0 = Bs[st][mm][kk + tig][nb + gid];
                    uint32_t b1 = Bs[st][mm][kk + tig + 4][nb + gid];
#pragma unroll
                    for (int mt = 0; mt < 2; mt++) {
                        mma_tf32(acc[mm][mt][nt][0], acc[mm][mt][nt][1],
                                 acc[mm][mt][nt][2], acc[mm][mt][nt][3],
                                 afr[mt][0], afr[mt][1], afr[mt][2], afr[mt][3], b0, b1);
                    }
                }
            }
        }
        __syncthreads();
        if (kt + 2 < F / BK) {
            copy_tile(kt + 2, st);
            cp_commit();
        }
    }

#pragma unroll
    for (int mm = 0; mm < 2; mm++) {
        const float* av = (mm == 0) ? a_ref : a_dir;
        uint32_t* outb = (mm == 0) ? g_whb_ref : g_whb_dir;
        float sp[2][2] = {{0.f, 0.f}, {0.f, 0.f}};
        float tp[2][2] = {{0.f, 0.f}, {0.f, 0.f}};

#pragma unroll
        for (int mt = 0; mt < 2; mt++) {
            int r0 = m0 + wm * 32 + mt * 16 + gid;
            int r1 = r0 + 8;
#pragma unroll
            for (int nt = 0; nt < 4; nt++) {
                int col = wn * 32 + nt * 8 + tig * 2;
                float as0 = av[col], as1 = av[col + 1];
                float an0 = av[128 + col], an1 = av[128 + col + 1];
                float c0 = acc[mm][mt][nt][0], c1 = acc[mm][mt][nt][1];
                float c2 = acc[mm][mt][nt][2], c3 = acc[mm][mt][nt][3];
                sp[mt][0] += c0 * as0 + c1 * as1;
                tp[mt][0] += c0 * an0 + c1 * an1;
                sp[mt][1] += c2 * as0 + c3 * as1;
                tp[mt][1] += c2 * an0 + c3 * an1;
                if (r0 < N) {
                    __nv_bfloat162 p = __float22bfloat162_rn(make_float2(c0, c1));
                    outb[(size_t)r0 * 64 + (col >> 1)] = *reinterpret_cast<uint32_t*>(&p);
                }
                if (r1 < N) {
                    __nv_bfloat162 p = __float22bfloat162_rn(make_float2(c2, c3));
                    outb[(size_t)r1 * 64 + (col >> 1)] = *reinterpret_cast<uint32_t*>(&p);
                }
            }
        }

#pragma unroll
        for (int mt = 0; mt < 2; mt++)
#pragma unroll
            for (int rr = 0; rr < 2; rr++) {
#pragma unroll
                for (int off = 1; off <= 2; off <<= 1) {
                    sp[mt][rr] += __shfl_xor_sync(0xffffffffu, sp[mt][rr], off);
                    tp[mt][rr] += __shfl_xor_sync(0xffffffffu, tp[mt][rr], off);
                }
                if (tig == 0) {
                    int lr = wm * 32 + mt * 16 + gid + rr * 8;
                    atomicAdd(&s_sm[mm][lr], sp[mt][rr]);
                    atomicAdd(&t_sm[mm][lr], tp[mt][rr]);
                }
            }
    }
    __syncthreads();

    if (tid < 128) {
        int mm = tid >> 6;
        int r = tid & 63;
        int gr = m0 + r;
        if (gr < N) {
            if (mm == 0) { g_s_ref[gr] = s_sm[0][r]; g_t_ref[gr] = t_sm[0][r]; }
            else         { g_s_dir[gr] = s_sm[1][r]; g_t_dir[gr] = t_sm[1][r]; }
        }
    }
}

// ---------------------------------------------------------------------------
// Kernel 2: fused attention + gather + sigmoid + average. One warp per node.
// R11 loop body verbatim; 64-thread CTAs (max-of-2 straggler granularity),
// 24 CTAs/SM for 75% theoretical occupancy.
// ---------------------------------------------------------------------------
__global__ __launch_bounds__(64, 24)
void gather_kernel(const int* __restrict__ ref_nb,   // [N,4,10]
                   const int* __restrict__ ref_cnt,  // [N,4]
                   const int* __restrict__ dir_nb,   // [N,32]
                   const int* __restrict__ dir_cnt,  // [N]
                   float* __restrict__ out,
                   int N)
{
    __shared__ float2 s_ref[2][40];
    __shared__ float2 s_dir[2][32];
    const unsigned FULL = 0xffffffffu;
    const int wid = threadIdx.x >> 5;
    const int lane = threadIdx.x & 31;
    const int n = (blockIdx.x * blockDim.x + threadIdx.x) >> 5;
    if (n >= N) return;

    int4 rc = *reinterpret_cast<const int4*>(&ref_cnt[n * 4]);
    int idx1 = ref_nb[(size_t)n * 40 + lane];
    int idx2 = (lane < 8) ? ref_nb[(size_t)n * 40 + 32 + lane] : 0;
    int dcnt = dir_cnt[n];
    int didx = dir_nb[(size_t)n * 32 + lane];
    float sref = g_s_ref[n];
    float sdir = g_s_dir[n];

    const int d1 = lane / 10;
    const int k1 = lane - d1 * 10;
    int cd1 = (d1 == 0) ? rc.x : (d1 == 1) ? rc.y : (d1 == 2) ? rc.z : rc.w;
    bool v1 = (k1 < cd1);
    bool v2 = (lane < 8) && ((lane + 2) < rc.w);
    bool dval = (lane < dcnt);

    float tv1 = v1 ? g_t_ref[idx1] : 0.f;
    float tv2 = v2 ? g_t_ref[idx2] : 0.f;
    float td  = dval ? g_t_dir[didx] : 0.f;

    float x1 = tv1 + __shfl_down_sync(FULL, tv1, 1);
    float x2 = x1 + __shfl_down_sync(FULL, x1, 2);
    float x4 = x2 + __shfl_down_sync(FULL, x2, 4);
    float b = tv2;
    b += __shfl_xor_sync(FULL, b, 1);
    b += __shfl_xor_sync(FULL, b, 2);
    b += __shfl_xor_sync(FULL, b, 4);
    float S0 = __shfl_sync(FULL, x4, 0)  + __shfl_sync(FULL, x1, 8);
    float S1 = __shfl_sync(FULL, x4, 10) + __shfl_sync(FULL, x1, 18);
    float S2 = __shfl_sync(FULL, x4, 20) + __shfl_sync(FULL, x1, 28);
    float S3 = __shfl_sync(FULL, x1, 30) + __shfl_sync(FULL, b, 0);

    float c0f = (float)max(rc.x, 1), c1f = (float)max(rc.y, 1);
    float c2f = (float)max(rc.z, 1), c3f = (float)max(rc.w, 1);
    float e0 = leakyf(sref + S0 / c0f);
    float e1 = leakyf(sref + S1 / c1f);
    float e2 = leakyf(sref + S2 / c2f);
    float e3 = leakyf(sref + S3 / c3f);
    float m4 = fmaxf(fmaxf(e0, e1), fmaxf(e2, e3));
    float x0e = __expf(e0 - m4), x1e = __expf(e1 - m4);
    float x2e = __expf(e2 - m4), x3e = __expf(e3 - m4);
    float den = x0e + x1e + x2e + x3e;
    float wd0 = x0e / (den * c0f), wd1 = x1e / (den * c1f);
    float wd2 = x2e / (den * c2f), wd3 = x3e / (den * c3f);

    float w1 = (d1 == 0) ? wd0 : (d1 == 1) ? wd1 : (d1 == 2) ? wd2 : wd3;
    float w2 = wd3;

    float exd = dval ? __expf(leakyf(sdir + td)) : 0.f;
    float dend = exd;
#pragma unroll
    for (int off = 16; off; off >>= 1) dend += __shfl_xor_sync(FULL, dend, off);
    float alpha = exd / dend;

    int P1 = rc.x, P2 = P1 + rc.y, P3 = P2 + rc.z;
    int nref = P3 + rc.w;
    int dst1 = ((d1 == 0) ? 0 : (d1 == 1) ? P1 : (d1 == 2) ? P2 : P3) + k1;
    if (v1) s_ref[wid][dst1] = make_float2(w1, __int_as_float(idx1));
    if (v2) s_ref[wid][P3 + lane + 2] = make_float2(w2, __int_as_float(idx2));
    s_dir[wid][lane] = make_float2(alpha, __int_as_float(didx));
    __syncwarp();

    const char* baseR = (const char*)g_whb_ref + (size_t)lane * 8;
    const char* baseD = (const char*)g_whb_dir + (size_t)lane * 8;
    unsigned long long aR01 = 0, aR23 = 0, aD01 = 0, aD23 = 0;

    int k = 0;
    for (; k + 4 <= dcnt; k += 4) {
        float2 p0 = s_dir[wid][k];
        float2 p1 = s_dir[wid][k + 1];
        float2 p2 = s_dir[wid][k + 2];
        float2 p3 = s_dir[wid][k + 3];
        uint2 v0 = *reinterpret_cast<const uint2*>(baseD + (size_t)__float_as_int(p0.y) * 256);
        uint2 v1_ = *reinterpret_cast<const uint2*>(baseD + (size_t)__float_as_int(p1.y) * 256);
        uint2 v2_ = *reinterpret_cast<const uint2*>(baseD + (size_t)__float_as_int(p2.y) * 256);
        uint2 v3 = *reinterpret_cast<const uint2*>(baseD + (size_t)__float_as_int(p3.y) * 256);
        unsigned long long w0 = packf2(p0.x, p0.x);
        unsigned long long w1_ = packf2(p1.x, p1.x);
        unsigned long long w2_ = packf2(p2.x, p2.x);
        unsigned long long w3 = packf2(p3.x, p3.x);
        ffma2(aD01, bf2f2(v0.x), w0);  ffma2(aD23, bf2f2(v0.y), w0);
        ffma2(aD01, bf2f2(v1_.x), w1_); ffma2(aD23, bf2f2(v1_.y), w1_);
        ffma2(aD01, bf2f2(v2_.x), w2_); ffma2(aD23, bf2f2(v2_.y), w2_);
        ffma2(aD01, bf2f2(v3.x), w3);  ffma2(aD23, bf2f2(v3.y), w3);
    }
    if (k + 2 <= dcnt) {
        float2 p0 = s_dir[wid][k];
        float2 p1 = s_dir[wid][k + 1];
        uint2 v0 = *reinterpret_cast<const uint2*>(baseD + (size_t)__float_as_int(p0.y) * 256);
        uint2 v1_ = *reinterpret_cast<const uint2*>(baseD + (size_t)__float_as_int(p1.y) * 256);
        unsigned long long w0 = packf2(p0.x, p0.x);
        unsigned long long w1_ = packf2(p1.x, p1.x);
        ffma2(aD01, bf2f2(v0.x), w0);  ffma2(aD23, bf2f2(v0.y), w0);
        ffma2(aD01, bf2f2(v1_.x), w1_); ffma2(aD23, bf2f2(v1_.y), w1_);
        k += 2;
    }
    if (k < dcnt) {
        float2 p = s_dir[wid][k];
        uint2 v = *reinterpret_cast<const uint2*>(baseD + (size_t)__float_as_int(p.y) * 256);
        unsigned long long w = packf2(p.x, p.x);
        ffma2(aD01, bf2f2(v.x), w); ffma2(aD23, bf2f2(v.y), w);
    }

    k = 0;
    for (; k + 4 <= nref; k += 4) {
        float2 p0 = s_ref[wid][k];
        float2 p1 = s_ref[wid][k + 1];
        float2 p2 = s_ref[wid][k + 2];
        float2 p3 = s_ref[wid][k + 3];
        uint2 v0 = *reinterpret_cast<const uint2*>(baseR + (size_t)__float_as_int(p0.y) * 256);
        uint2 v1_ = *reinterpret_cast<const uint2*>(baseR + (size_t)__float_as_int(p1.y) * 256);
        uint2 v2_ = *reinterpret_cast<const uint2*>(baseR + (size_t)__float_as_int(p2.y) * 256);
        uint2 v3 = *reinterpret_cast<const uint2*>(baseR + (size_t)__float_as_int(p3.y) * 256);
        unsigned long long w0 = packf2(p0.x, p0.x);
        unsigned long long w1_ = packf2(p1.x, p1.x);
        unsigned long long w2_ = packf2(p2.x, p2.x);
        unsigned long long w3 = packf2(p3.x, p3.x);
        ffma2(aR01, bf2f2(v0.x), w0);  ffma2(aR23, bf2f2(v0.y), w0);
        ffma2(aR01, bf2f2(v1_.x), w1_); ffma2(aR23, bf2f2(v1_.y), w1_);
        ffma2(aR01, bf2f2(v2_.x), w2_); ffma2(aR23, bf2f2(v2_.y), w2_);
        ffma2(aR01, bf2f2(v3.x), w3);  ffma2(aR23, bf2f2(v3.y), w3);
    }
    if (k + 2 <= nref) {
        float2 p0 = s_ref[wid][k];
        float2 p1 = s_ref[wid][k + 1];
        uint2 v0 = *reinterpret_cast<const uint2*>(baseR + (size_t)__float_as_int(p0.y) * 256);
        uint2 v1_ = *reinterpret_cast<const uint2*>(baseR + (size_t)__float_as_int(p1.y) * 256);
        unsigned long long w0 = packf2(p0.x, p0.x);
        unsigned long long w1_ = packf2(p1.x, p1.x);
        ffma2(aR01, bf2f2(v0.x), w0);  ffma2(aR23, bf2f2(v0.y), w0);
        ffma2(aR01, bf2f2(v1_.x), w1_); ffma2(aR23, bf2f2(v1_.y), w1_);
        k += 2;
    }
    if (k < nref) {
        float2 p = s_ref[wid][k];
        uint2 v = *reinterpret_cast<const uint2*>(baseR + (size_t)__float_as_int(p.y) * 256);
        unsigned long long w = packf2(p.x, p.x);
        ffma2(aR01, bf2f2(v.x), w); ffma2(aR23, bf2f2(v.y), w);
    }

    float2 r01 = *reinterpret_cast<float2*>(&aR01);
    float2 r23 = *reinterpret_cast<float2*>(&aR23);
    float2 d01 = *reinterpret_cast<float2*>(&aD01);
    float2 d23 = *reinterpret_cast<float2*>(&aD23);

    float4 o;
    o.x = 0.5f * (sigmoidf_(r01.x) + sigmoidf_(d01.x));
    o.y = 0.5f * (sigmoidf_(r01.y) + sigmoidf_(d01.y));
    o.z = 0.5f * (sigmoidf_(r23.x) + sigmoidf_(d23.x));
    o.w = 0.5f * (sigmoidf_(r23.y) + sigmoidf_(d23.y));
    *reinterpret_cast<float4*>(&out[(size_t)n * F + lane * 4]) = o;
}

// ---------------------------------------------------------------------------
extern "C" void kernel_launch(void* const* d_in, const int* in_sizes, int n_in,
                              void* d_out, int out_size)
{
    const float* h     = (const float*)d_in[0];
    const float* W_ref = (const float*)d_in[1];
    const float* a_ref = (const float*)d_in[2];
    const float* W_dir = (const float*)d_in[3];
    const float* a_dir = (const float*)d_in[4];
    const int* ref_nb  = (const int*)d_in[5];
    const int* ref_cnt = (const int*)d_in[6];
    const int* dir_nb  = (const int*)d_in[7];
    const int* dir_cnt = (const int*)d_in[8];
    float* out = (float*)d_out;

    const int N = in_sizes[0] / F;

    gemm_tf32_kernel<<<(N + 63) / 64, 256>>>(h, W_ref, W_dir, a_ref, a_dir, N);

    const int nwb = (N * 32 + 63) / 64;  // one warp per node, 2 warps/block
    gather_kernel<<<nwb, 64>>>(ref_nb, ref_cnt, dir_nb, dir_cnt, out, N);
}